// round 6
// baseline (speedup 1.0000x reference)
#include <cuda_runtime.h>
#include <cuda_fp16.h>
#include <math.h>
#include <stdint.h>

#define D_TOT   147456
#define N_MEM   6
#define HW      64
#define NPX     4096
#define SRH     72                  // smem row stride in halves (144 B)

// ---------------- device scratch (no allocation allowed) -------------------
__device__ float  g_minmax[2];
__device__ float  g_m1[D_TOT];
__device__ float  g_g1[D_TOT];                  // shared level-1 gate
__device__ __half g_w2[N_MEM * 9 * 128 * 128];  // [n][tap][oc][ic] fp16
__device__ __half g_xh[48 * NPX * 128];         // [s][px][ic] NHWC fp16

// ---------------- helpers ---------------------------------------------------
__device__ __forceinline__ uint32_t smem_u32(const void* p) {
    uint32_t a;
    asm("{ .reg .u64 t; cvta.to.shared.u64 t, %1; cvt.u32.u64 %0, t; }"
        : "=r"(a) : "l"(p));
    return a;
}
__device__ __forceinline__ void cp16(uint32_t dst, const void* src, uint32_t sz) {
    asm volatile("cp.async.cg.shared.global [%0], [%1], 16, %2;"
                 :: "r"(dst), "l"(src), "r"(sz) : "memory");
}
__device__ __forceinline__ void ldm4(uint32_t& r0, uint32_t& r1,
                                     uint32_t& r2, uint32_t& r3, uint32_t a) {
    asm volatile("ldmatrix.sync.aligned.m8n8.x4.shared.b16 {%0,%1,%2,%3}, [%4];"
                 : "=r"(r0), "=r"(r1), "=r"(r2), "=r"(r3) : "r"(a));
}
__device__ __forceinline__ void mma16(float4& d, const uint32_t* a,
                                      uint32_t b0, uint32_t b1) {
    asm volatile(
        "mma.sync.aligned.m16n8k16.row.col.f32.f16.f16.f32 "
        "{%0,%1,%2,%3},{%4,%5,%6,%7},{%8,%9},{%0,%1,%2,%3};"
        : "+f"(d.x), "+f"(d.y), "+f"(d.z), "+f"(d.w)
        : "r"(a[0]), "r"(a[1]), "r"(a[2]), "r"(a[3]), "r"(b0), "r"(b1));
}

// ---------------------------------------------------------------------------
// Stage 0: global max/min of U
// ---------------------------------------------------------------------------
__global__ void init_minmax_kernel() { g_minmax[0] = -INFINITY; g_minmax[1] = INFINITY; }

__device__ __forceinline__ void atomicMaxF(float* a, float v) {
    if (v >= 0.f) atomicMax((int*)a, __float_as_int(v));
    else          atomicMin((unsigned int*)a, __float_as_uint(v));
}
__device__ __forceinline__ void atomicMinF(float* a, float v) {
    if (v >= 0.f) atomicMin((int*)a, __float_as_int(v));
    else          atomicMax((unsigned int*)a, __float_as_uint(v));
}

__global__ void reduce_minmax_kernel(const float* __restrict__ U, int n) {
    float mx = -INFINITY, mn = INFINITY;
    for (int i = blockIdx.x * blockDim.x + threadIdx.x; i < n; i += gridDim.x * blockDim.x) {
        float v = U[i]; mx = fmaxf(mx, v); mn = fminf(mn, v);
    }
#pragma unroll
    for (int o = 16; o; o >>= 1) {
        mx = fmaxf(mx, __shfl_xor_sync(0xffffffffu, mx, o));
        mn = fminf(mn, __shfl_xor_sync(0xffffffffu, mn, o));
    }
    if ((threadIdx.x & 31) == 0) { atomicMaxF(&g_minmax[0], mx); atomicMinF(&g_minmax[1], mn); }
}

// ---------------------------------------------------------------------------
// Stage 1: m1 + shared gate g1
// ---------------------------------------------------------------------------
__device__ __forceinline__ float stable_sigmoid(float x) {
    if (x >= 0.f) return 1.f / (1.f + __expf(-x));
    float e = __expf(x); return e / (1.f + e);
}
__device__ __forceinline__ float gatef(float uu, float b) {
    float g  = __logf(uu / (1.f - uu));
    float bs = stable_sigmoid(g + b);
    float t  = __fadd_rn(__fmul_rn(bs, 1.4f), -0.2f);
    return fminf(fmaxf(t, 0.f), 1.f);
}

__global__ void compute_m1_kernel(const float* __restrict__ U,
                                  const float* __restrict__ bp,
                                  const float* __restrict__ uu) {
    int d = blockIdx.x * blockDim.x + threadIdx.x;
    if (d >= D_TOT) return;
    float s1 = (g_minmax[0] - g_minmax[1]) / 3.0f;
    float s = 0.f;
#pragma unroll
    for (int nn = 0; nn < N_MEM; nn++) s += s1 * rintf(U[nn * D_TOT + d] / s1);
    g_m1[d] = s * (1.0f / 6.0f);
    g_g1[d] = gatef(uu[6 * D_TOT + d], bp[6 * D_TOT + d]);
}

// ---------------------------------------------------------------------------
// Stage 2: gates + residual quantization -> g_w2 [n][tap][oc][ic] fp16
// ---------------------------------------------------------------------------
__global__ void compute_w_kernel(const float* __restrict__ U,
                                 const float* __restrict__ bp,
                                 const float* __restrict__ uu) {
    int idx = blockIdx.x * blockDim.x + threadIdx.x;
    if (idx >= N_MEM * D_TOT) return;
    int nn = idx / D_TOT;
    int d  = idx - nn * D_TOT;

    float s1 = (g_minmax[0] - g_minmax[1]) / 3.0f;
    float s2 = s1 / 5.0f;

    float Uv = U[idx];
    float v1 = s1 * rintf(Uv / s1);
    float v2 = s2 * rintf((Uv - g_m1[d]) / s2);

    float g0 = gatef(uu[idx], bp[idx]);
    float w = v1 * g0 + ((g0 > 0.f) ? v2 * g_g1[d] : 0.f);

    int oc  = d / 1152;
    int rem = d - oc * 1152;
    int ic  = rem / 9;
    int tap = rem - ic * 9;
    g_w2[(((size_t)nn * 9 + tap) * 128 + oc) * 128 + ic] = __float2half_rn(w);
}

// ---------------------------------------------------------------------------
// Stage 3: NCHW -> NHWC transpose, fp16
// ---------------------------------------------------------------------------
__global__ void transpose_kernel(const float* __restrict__ x) {
    __shared__ float t[32][33];
    int s   = blockIdx.z;
    int px0 = blockIdx.x * 32;
    int ic0 = blockIdx.y * 32;
    const float* xs = x + (size_t)s * 128 * NPX;
#pragma unroll
    for (int j = 0; j < 4; j++) {
        int ic = ic0 + threadIdx.y + j * 8;
        t[threadIdx.y + j * 8][threadIdx.x] = xs[(size_t)ic * NPX + px0 + threadIdx.x];
    }
    __syncthreads();
    __half* xd = g_xh + (size_t)s * NPX * 128;
#pragma unroll
    for (int j = 0; j < 4; j++) {
        int px = px0 + threadIdx.y + j * 8;
        xd[(size_t)px * 128 + ic0 + threadIdx.x] =
            __float2half_rn(t[threadIdx.x][threadIdx.y + j * 8]);
    }
}

// ---------------------------------------------------------------------------
// Stage 4: fp16 mma.sync m16n8k16 implicit-GEMM conv
//   CTA: 128 oc x 256 px, 16 warps (warp tile 64x32), K=1152 in 18 stages,
//   4-deep cp.async ring, one __syncthreads per stage. 512 threads.
// ---------------------------------------------------------------------------
#define WB_BYTES (128 * SRH * 2)           // 18432
#define BUF_BYTES (384 * SRH * 2)          // 55296
#define SM_BYTES (4 * BUF_BYTES)           // 221184

__device__ __forceinline__ void issue_stage(int stg, uint32_t sbase, int tid,
                                            const __half* wbase, const __half* xbase,
                                            int y0) {
    int tap = stg >> 1, h = stg & 1;
    int dy = tap / 3 - 1, dx = tap % 3 - 1;
    const __half* wsrc = wbase + (size_t)tap * 128 * 128 + h * 64;
    uint32_t wdst = sbase + (uint32_t)(stg & 3) * BUF_BYTES;
    uint32_t xdst = wdst + WB_BYTES;
#pragma unroll
    for (int i = 0; i < 2; i++) {                   // W: 128 rows x 8 chunks
        int idx = tid + i * 512;
        int row = idx >> 3, j = idx & 7;
        cp16(wdst + row * (SRH * 2) + j * 16, wsrc + (size_t)row * 128 + j * 8, 16);
    }
#pragma unroll
    for (int i = 0; i < 4; i++) {                   // X: 256 rows x 8 chunks
        int idx = tid + i * 512;
        int r = idx >> 3, j = idx & 7;
        int gy = y0 + (r >> 6) + dy;
        int gx = (r & 63) + dx;
        bool ok = ((unsigned)gy < 64u) && ((unsigned)gx < 64u);
        const __half* src = xbase + (size_t)(ok ? gy * 64 + gx : 0) * 128 + h * 64 + j * 8;
        cp16(xdst + r * (SRH * 2) + j * 16, src, ok ? 16u : 0u);
    }
    asm volatile("cp.async.commit_group;" ::: "memory");
}

__global__ __launch_bounds__(512, 1)
void conv_kernel(float* __restrict__ out) {
    extern __shared__ __half smh[];
    uint32_t sbase = smem_u32(smh);

    const int tid = threadIdx.x;
    const int s   = blockIdx.y;
    const int n   = s % N_MEM;
    const int y0  = blockIdx.x * 4;          // 4 image rows per CTA (256 px)

    const int w   = tid >> 5;
    const int l   = tid & 31;
    const int grp = l >> 2, thr = l & 3;
    const int ocb = (w & 1) * 64;            // 2 oc-halves
    const int pxb = (w >> 1) * 32;           // 8 px-blocks of 32

    // ldmatrix lane addresses (byte offsets within buffer)
    const uint32_t aoff = (uint32_t)((ocb + (l & 7) + ((l >> 3) & 1) * 8) * (SRH * 2)
                                     + (l >> 4) * 16);
    const uint32_t boff = (uint32_t)(WB_BYTES
                                     + (pxb + (l & 7) + ((l >> 4) & 1) * 8) * (SRH * 2)
                                     + ((l >> 3) & 1) * 16);

    const __half* wbase = g_w2 + (size_t)n * 9 * 128 * 128;
    const __half* xbase = g_xh + (size_t)s * NPX * 128;

    float4 acc[4][4];
#pragma unroll
    for (int i = 0; i < 4; i++)
#pragma unroll
        for (int j = 0; j < 4; j++) acc[i][j] = make_float4(0.f, 0.f, 0.f, 0.f);

    issue_stage(0, sbase, tid, wbase, xbase, y0);
    issue_stage(1, sbase, tid, wbase, xbase, y0);
    issue_stage(2, sbase, tid, wbase, xbase, y0);

    for (int st = 0; st < 18; st++) {
        asm volatile("cp.async.wait_group 2;" ::: "memory");
        __syncthreads();

        if (st + 3 < 18)
            issue_stage(st + 3, sbase, tid, wbase, xbase, y0);

        uint32_t bufb = sbase + (uint32_t)(st & 3) * BUF_BYTES;
        uint32_t aA = bufb + aoff;
        uint32_t aB = bufb + boff;

#pragma unroll
        for (int ks = 0; ks < 4; ks++) {            // 4 k16 blocks in K=64
            uint32_t a[4][4];
#pragma unroll
            for (int mt = 0; mt < 4; mt++)
                ldm4(a[mt][0], a[mt][1], a[mt][2], a[mt][3],
                     aA + mt * 16 * (SRH * 2) + ks * 32);
#pragma unroll
            for (int ntp = 0; ntp < 2; ntp++) {
                uint32_t b0, b1, b2, b3;
                ldm4(b0, b1, b2, b3, aB + ntp * 16 * (SRH * 2) + ks * 32);
#pragma unroll
                for (int mt = 0; mt < 4; mt++) {
                    mma16(acc[mt][2 * ntp],     a[mt], b0, b1);
                    mma16(acc[mt][2 * ntp + 1], a[mt], b2, b3);
                }
            }
        }
    }

    // epilogue: float2 stores, NCHW output
    float* ob = out + (size_t)s * 128 * NPX;
#pragma unroll
    for (int mt = 0; mt < 4; mt++) {
        int oc = ocb + mt * 16 + grp;
#pragma unroll
        for (int nt = 0; nt < 4; nt++) {
            int px = pxb + nt * 8 + 2 * thr;
            float* op = ob + (size_t)oc * NPX + (y0 + (px >> 6)) * 64 + (px & 63);
            float4 d = acc[mt][nt];
            *(float2*)op = make_float2(d.x, d.y);
            *(float2*)(op + 8 * NPX) = make_float2(d.z, d.w);
        }
    }
}

// ---------------------------------------------------------------------------
extern "C" void kernel_launch(void* const* d_in, const int* in_sizes, int n_in,
                              void* d_out, int out_size) {
    const float* x  = (const float*)d_in[0];   // (48,128,64,64)
    const float* U  = (const float*)d_in[1];   // (6, 147456)
    const float* bp = (const float*)d_in[2];   // (7, 147456)
    const float* u  = (const float*)d_in[3];   // (7, 147456)
    float* out = (float*)d_out;                // (48,128,64,64)

    cudaFuncSetAttribute(conv_kernel, cudaFuncAttributeMaxDynamicSharedMemorySize, SM_BYTES);

    init_minmax_kernel<<<1, 1>>>();
    reduce_minmax_kernel<<<432, 256>>>(U, N_MEM * D_TOT);
    compute_m1_kernel<<<(D_TOT + 255) / 256, 256>>>(U, bp, u);
    compute_w_kernel<<<(N_MEM * D_TOT + 255) / 256, 256>>>(U, bp, u);
    transpose_kernel<<<dim3(128, 4, 48), dim3(32, 8)>>>(x);

    conv_kernel<<<dim3(16, 48), 512, SM_BYTES>>>(out);
}